// round 17
// baseline (speedup 1.0000x reference)
#include <cuda_runtime.h>
#include <cuda_fp16.h>
#include <mma.h>
#include <cstdint>

using namespace nvcuda;

#define NN   50000
#define EE   800000
#define NG   500
#define C    100
#define KIN  33
#define OUTC 200
#define BN_EPS 1e-5f

// ---------------- scratch (device globals; no allocations) ----------------
__device__ int    d_fmt64;
__device__ int    d_ticket;                   // statically 0; self-resetting
__device__ int    d_src[EE];
__device__ int    d_dst[EE];
__device__ int    d_batch[NN];
__device__ int    d_indeg[NN];
__device__ int    d_row[NN + 1];
__device__ int    d_cursor[NN];
__device__ unsigned long long d_e[EE];        // packed {w_bits<<32 | src}
__device__ float  d_dinv[NN];
__device__ int    d_gstart[NG + 1];
#define SBLK 196
__device__ int    d_bsum[SBLK];
__device__ int    d_boff[SBLK];
__device__ float  d_aggx[NN * KIN];
__device__ __align__(16) float  d_m[NN * C];
__device__ __align__(16) float  d_agg[NN * C];
#define SGRID 391                             // ceil(NN/128)
__device__ float  d_psum[SGRID * C];
__device__ float  d_psq[SGRID * C];
__device__ __align__(16) float  d_scale[C];
__device__ __align__(16) float  d_shift[C];

// ---------------- init: zero indeg + parallel format detect ----------------
__global__ void k_init(const long long* __restrict__ ei) {
    int i = blockIdx.x * blockDim.x + threadIdx.x;
    if (i < NN) d_indeg[i] = 0;
    if (blockIdx.x == 0) {
        __shared__ int bad;
        if (threadIdx.x == 0) bad = 0;
        __syncthreads();
        if (threadIdx.x < 64) {
            long long v = ei[threadIdx.x];
            if (v < 0 || v >= NN) atomicAdd(&bad, 1);
        }
        __syncthreads();
        if (threadIdx.x == 0) d_fmt64 = (bad == 0);
    }
}

__global__ void k_prep(const void* __restrict__ eiv, const void* __restrict__ bv) {
    int t = blockIdx.x * blockDim.x + threadIdx.x;
    int f = d_fmt64;
    if (t < EE) {
        int s, d;
        if (f) {
            const long long* p = (const long long*)eiv;
            s = (int)p[t]; d = (int)p[EE + t];
        } else {
            const int* p = (const int*)eiv;
            s = p[t]; d = p[EE + t];
        }
        if ((unsigned)s >= NN) s = 0;
        if ((unsigned)d >= NN) d = 0;
        d_src[t] = s;
        d_dst[t] = d;
        atomicAdd(&d_indeg[d], 1);
    }
    if (t < NN) {
        int g;
        if (f) g = (int)((const long long*)bv)[t];
        else   g = ((const int*)bv)[t];
        if ((unsigned)g >= NG) g = 0;
        d_batch[t] = g;
    }
}

// ---------------- scanA+scanB fused (ticketed last block) ----------------
__global__ void k_scanAB() {
    __shared__ int sh[256];
    __shared__ int is_last;
    int t = threadIdx.x;
    int i = blockIdx.x * 256 + t;
    sh[t] = (i < NN) ? d_indeg[i] : 0;
    __syncthreads();
    for (int off = 128; off > 0; off >>= 1) {
        if (t < off) sh[t] += sh[t + off];
        __syncthreads();
    }
    if (t == 0) d_bsum[blockIdx.x] = sh[0];
    __threadfence();
    if (t == 0) is_last = (atomicAdd(&d_ticket, 1) == gridDim.x - 1);
    __syncthreads();
    if (is_last) {
        int mine = (t < SBLK) ? d_bsum[t] : 0;
        sh[t] = mine;
        __syncthreads();
        for (int off = 1; off < 256; off <<= 1) {
            int v = (t >= off) ? sh[t - off] : 0;
            __syncthreads();
            sh[t] += v;
            __syncthreads();
        }
        if (t < SBLK) d_boff[t] = sh[t] - mine;
        if (t == 0) d_ticket = 0;
    }
}

__global__ void k_scanC() {
    __shared__ int sh[256];
    int t = threadIdx.x;
    int i = blockIdx.x * 256 + t;
    int v = (i < NN) ? d_indeg[i] : 0;
    sh[t] = v;
    __syncthreads();
    for (int off = 1; off < 256; off <<= 1) {
        int u = (t >= off) ? sh[t - off] : 0;
        __syncthreads();
        sh[t] += u;
        __syncthreads();
    }
    if (i < NN) {
        int excl = sh[t] - v + d_boff[blockIdx.x];
        d_row[i] = excl;
        d_cursor[i] = excl;
        d_dinv[i] = rsqrtf((float)(v + 1));
        if (i == NN - 1) d_row[NN] = EE;
    }
}

#define FILL_BLKS 3125
__global__ void k_fillb() {
    if (blockIdx.x < FILL_BLKS) {
        int e = blockIdx.x * 256 + threadIdx.x;
        if (e < EE) {
            int s = d_src[e], d = d_dst[e];
            int p = atomicAdd(&d_cursor[d], 1);
            float w = d_dinv[s] * d_dinv[d];
            d_e[p] = ((unsigned long long)__float_as_uint(w) << 32) | (unsigned)s;
        }
    } else {
        int g = (blockIdx.x - FILL_BLKS) * 256 + threadIdx.x;
        if (g > NG) return;
        int lo = 0, hi = NN;
        while (lo < hi) {
            int mid = (lo + hi) >> 1;
            if (d_batch[mid] < g) lo = mid + 1; else hi = mid;
        }
        d_gstart[g] = lo;
    }
}

// ---------------- layer-0 gather on raw x ----------------
__global__ void k_gatherX(const float* __restrict__ x) {
    int warp = (blockIdx.x * blockDim.x + threadIdx.x) >> 5;
    int lane = threadIdx.x & 31;
    if (warp >= NN) return;
    const int beg = d_row[warp], end = d_row[warp + 1];
    float dv = d_dinv[warp];
    float d2 = dv * dv;
    float a0 = d2 * x[(size_t)warp * KIN + lane];
    float a1 = (lane == 0) ? d2 * x[(size_t)warp * KIN + 32] : 0.0f;
    int e = beg;
    for (; e + 3 < end; e += 4) {
        unsigned long long v0 = d_e[e],     v1 = d_e[e + 1];
        unsigned long long v2 = d_e[e + 2], v3 = d_e[e + 3];
        int s0 = (int)(unsigned)v0, s1 = (int)(unsigned)v1;
        int s2 = (int)(unsigned)v2, s3 = (int)(unsigned)v3;
        float w0 = __uint_as_float((unsigned)(v0 >> 32));
        float w1 = __uint_as_float((unsigned)(v1 >> 32));
        float w2 = __uint_as_float((unsigned)(v2 >> 32));
        float w3 = __uint_as_float((unsigned)(v3 >> 32));
        a0 = fmaf(w0, x[(size_t)s0 * KIN + lane], a0);
        a0 = fmaf(w1, x[(size_t)s1 * KIN + lane], a0);
        a0 = fmaf(w2, x[(size_t)s2 * KIN + lane], a0);
        a0 = fmaf(w3, x[(size_t)s3 * KIN + lane], a0);
        if (lane == 0) {
            a1 = fmaf(w0, x[(size_t)s0 * KIN + 32], a1);
            a1 = fmaf(w1, x[(size_t)s1 * KIN + 32], a1);
            a1 = fmaf(w2, x[(size_t)s2 * KIN + 32], a1);
            a1 = fmaf(w3, x[(size_t)s3 * KIN + 32], a1);
        }
    }
    for (; e < end; e++) {
        unsigned long long v0 = d_e[e];
        int s0 = (int)(unsigned)v0;
        float w0 = __uint_as_float((unsigned)(v0 >> 32));
        a0 = fmaf(w0, x[(size_t)s0 * KIN + lane], a0);
        if (lane == 0) a1 = fmaf(w0, x[(size_t)s0 * KIN + 32], a1);
    }
    d_aggx[(size_t)warp * KIN + lane] = a0;
    if (lane == 0) d_aggx[(size_t)warp * KIN + 32] = a1;
}

// ---------------- layer-0 GEMM (K=33), SIMT ----------------
#define MT  32
#define KCP 52
__global__ void k_gemm(const float* __restrict__ W,
                       const float* __restrict__ bvec,
                       int K, int mode)
{
    __shared__ __align__(16) float Ws[KCP][C];
    __shared__ __align__(16) float Hs[MT][KCP];
    const int tx  = threadIdx.x;
    const int ty  = threadIdx.y;
    const int tid = ty * 25 + tx;
    const int m0  = blockIdx.x * MT;

    float acc[4][4];
#pragma unroll
    for (int i = 0; i < 4; i++)
#pragma unroll
        for (int j = 0; j < 4; j++) acc[i][j] = 0.0f;

    for (int k0 = 0; k0 < K; k0 += KCP) {
        const int kc  = min(KCP, K - k0);
        const int kc4 = (kc + 3) & ~3;
        for (int idx = tid; idx < kc4 * C; idx += 200) {
            int kk = idx / C, cc = idx - kk * C;
            Ws[kk][cc] = (kk < kc) ? W[(size_t)(k0 + kk) * C + cc] : 0.0f;
        }
        for (int idx = tid; idx < MT * kc4; idx += 200) {
            int rr = idx / kc4, kk = idx - rr * kc4;
            int r = m0 + rr;
            float v = 0.0f;
            if (r < NN && kk < kc) {
                int ch = k0 + kk;
                if (mode) v = d_aggx[(size_t)r * KIN + ch];
                else {
                    v = d_agg[(size_t)r * C + ch];
                    v = fmaxf(fmaf(v, d_scale[ch], d_shift[ch]), 0.0f);
                }
            }
            Hs[rr][kk] = v;
        }
        __syncthreads();

        for (int k4 = 0; k4 < kc4; k4 += 4) {
            float4 w0 = *(const float4*)&Ws[k4 + 0][tx * 4];
            float4 w1 = *(const float4*)&Ws[k4 + 1][tx * 4];
            float4 w2 = *(const float4*)&Ws[k4 + 2][tx * 4];
            float4 w3 = *(const float4*)&Ws[k4 + 3][tx * 4];
#pragma unroll
            for (int i = 0; i < 4; i++) {
                float4 h = *(const float4*)&Hs[ty * 4 + i][k4];
                acc[i][0] = fmaf(h.x, w0.x, acc[i][0]);
                acc[i][1] = fmaf(h.x, w0.y, acc[i][1]);
                acc[i][2] = fmaf(h.x, w0.z, acc[i][2]);
                acc[i][3] = fmaf(h.x, w0.w, acc[i][3]);
                acc[i][0] = fmaf(h.y, w1.x, acc[i][0]);
                acc[i][1] = fmaf(h.y, w1.y, acc[i][1]);
                acc[i][2] = fmaf(h.y, w1.z, acc[i][2]);
                acc[i][3] = fmaf(h.y, w1.w, acc[i][3]);
                acc[i][0] = fmaf(h.z, w2.x, acc[i][0]);
                acc[i][1] = fmaf(h.z, w2.y, acc[i][1]);
                acc[i][2] = fmaf(h.z, w2.z, acc[i][2]);
                acc[i][3] = fmaf(h.z, w2.w, acc[i][3]);
                acc[i][0] = fmaf(h.w, w3.x, acc[i][0]);
                acc[i][1] = fmaf(h.w, w3.y, acc[i][1]);
                acc[i][2] = fmaf(h.w, w3.z, acc[i][2]);
                acc[i][3] = fmaf(h.w, w3.w, acc[i][3]);
            }
        }
        __syncthreads();
    }

    const int c0 = tx * 4;
    if (mode) {
        const float4 b4 = *(const float4*)&bvec[c0];
#pragma unroll
        for (int i = 0; i < 4; i++) {
            int r = m0 + ty * 4 + i;
            if (r < NN)
                *(float4*)&d_agg[(size_t)r * C + c0] =
                    make_float4(acc[i][0] + b4.x, acc[i][1] + b4.y,
                                acc[i][2] + b4.z, acc[i][3] + b4.w);
        }
    } else {
#pragma unroll
        for (int i = 0; i < 4; i++) {
            int r = m0 + ty * 4 + i;
            if (r < NN)
                *(float4*)&d_m[(size_t)r * C + c0] =
                    make_float4(acc[i][0], acc[i][1], acc[i][2], acc[i][3]);
        }
    }
}

// ============ WMMA K=100 GEMM v3: direct-to-global fragment stores ===========
#define MTW   128
#define NP    112
#define APAD  120
#define ABYTES (MTW * APAD * 2)        // 30720
#define BBYTES (NP * APAD * 2)         // 26880
#define WSTB   (8 * 256 * 4)           // per-warp 16x16 f32 staging: 8192
#define SMW   (ABYTES + BBYTES + WSTB) // 65792

__global__ void __launch_bounds__(256, 3)
k_gemm100_wmma(const float* __restrict__ W)
{
    extern __shared__ __align__(16) char smbuf[];
    __half* Asm = (__half*)smbuf;                      // [128][120]
    __half* Bsm = (__half*)(smbuf + ABYTES);           // [112][120]
    float*  Wst = (float*)(smbuf + ABYTES + BBYTES);   // [8][16][16]

    const int tid  = threadIdx.x;
    const int wid  = tid >> 5;
    const int lane = tid & 31;
    const int r0b  = blockIdx.x * MTW;

    // A tile: 128 rows x 28 quads (q<25 real -> BN+ReLU, else zero)
    for (int idx = tid; idx < MTW * 28; idx += 256) {
        int row = idx / 28, q = idx - row * 28;
        int r = r0b + row;
        __half2 h0 = __float2half2_rn(0.f), h1 = h0;
        if (r < NN && q < 25) {
            float4 a  = *(const float4*)&d_agg[(size_t)r * C + q * 4];
            float4 sc = *(const float4*)&d_scale[q * 4];
            float4 sh = *(const float4*)&d_shift[q * 4];
            h0 = __floats2half2_rn(fmaxf(fmaf(a.x, sc.x, sh.x), 0.f),
                                   fmaxf(fmaf(a.y, sc.y, sh.y), 0.f));
            h1 = __floats2half2_rn(fmaxf(fmaf(a.z, sc.z, sh.z), 0.f),
                                   fmaxf(fmaf(a.w, sc.w, sh.w), 0.f));
        }
        *(uint2*)&Asm[row * APAD + q * 4] =
            make_uint2(*(unsigned*)&h0, *(unsigned*)&h1);
    }
    // B tile: 112 rows x 28 quads (k<100 && q<25 real)
    for (int idx = tid; idx < NP * 28; idx += 256) {
        int k = idx / 28, q = idx - k * 28;
        __half2 h0 = __float2half2_rn(0.f), h1 = h0;
        if (k < C && q < 25) {
            float4 wv = *(const float4*)&W[(size_t)k * C + q * 4];
            h0 = __floats2half2_rn(wv.x, wv.y);
            h1 = __floats2half2_rn(wv.z, wv.w);
        }
        *(uint2*)&Bsm[k * APAD + q * 4] =
            make_uint2(*(unsigned*)&h0, *(unsigned*)&h1);
    }
    __syncthreads();

    wmma::fragment<wmma::accumulator, 16, 16, 16, float> acc[7];
#pragma unroll
    for (int nt = 0; nt < 7; nt++) wmma::fill_fragment(acc[nt], 0.0f);

#pragma unroll
    for (int kt = 0; kt < 7; kt++) {
        wmma::fragment<wmma::matrix_a, 16, 16, 16, __half, wmma::row_major> af;
        wmma::load_matrix_sync(af, &Asm[(wid * 16) * APAD + kt * 16], APAD);
#pragma unroll
        for (int nt = 0; nt < 7; nt++) {
            wmma::fragment<wmma::matrix_b, 16, 16, 16, __half, wmma::row_major> bf;
            wmma::load_matrix_sync(bf, &Bsm[(kt * 16) * APAD + nt * 16], APAD);
            wmma::mma_sync(acc[nt], af, bf, acc[nt]);
        }
    }

    float* wst = Wst + wid * 256;
    const int rw = r0b + wid * 16;
    if (r0b + MTW <= NN) {
        // fast path: tiles 0..5 straight to global (ldm = C = 100, mult of 4)
#pragma unroll
        for (int nt = 0; nt < 6; nt++)
            wmma::store_matrix_sync(&d_m[(size_t)rw * C + nt * 16], acc[nt],
                                    C, wmma::mem_row_major);
        // ragged tile 6: cols 96..99 via per-warp staging
        wmma::store_matrix_sync(wst, acc[6], 16, wmma::mem_row_major);
        __syncwarp();
        for (int i = lane; i < 64; i += 32) {
            int row = i >> 2, col = i & 3;
            d_m[(size_t)(rw + row) * C + 96 + col] = wst[row * 16 + col];
        }
    } else {
        // boundary block: everything staged + guarded
        for (int nt = 0; nt < 7; nt++) {
            wmma::store_matrix_sync(wst, acc[nt], 16, wmma::mem_row_major);
            __syncwarp();
            int ncols = (nt == 6) ? 4 : 16;
            for (int i = lane; i < 16 * ncols; i += 32) {
                int row = i / ncols, col = i - row * ncols;
                int r = rw + row;
                if (r < NN)
                    d_m[(size_t)r * C + nt * 16 + col] = wst[row * 16 + col];
            }
            __syncwarp();
        }
    }
}

// ---------------- gather (layers 1-3): fp32, unroll 4 ----------------
__global__ void k_gather(const float* __restrict__ bvec) {
    int warp = (blockIdx.x * blockDim.x + threadIdx.x) >> 5;
    int lane = threadIdx.x & 31;
    if (warp >= NN) return;
    const int beg = d_row[warp], end = d_row[warp + 1];
    const bool active = lane < 25;
    float4 acc = make_float4(0.f, 0.f, 0.f, 0.f);
    if (active) {
        float dv = d_dinv[warp];
        float d2 = dv * dv;
        const float4 mv = *(const float4*)&d_m[(size_t)warp * C + lane * 4];
        const float4 b4 = *(const float4*)&bvec[lane * 4];
        acc = make_float4(fmaf(d2, mv.x, b4.x), fmaf(d2, mv.y, b4.y),
                          fmaf(d2, mv.z, b4.z), fmaf(d2, mv.w, b4.w));
    }
    int e = beg;
    for (; e + 3 < end; e += 4) {
        unsigned long long v0 = d_e[e],     v1 = d_e[e + 1];
        unsigned long long v2 = d_e[e + 2], v3 = d_e[e + 3];
        int s0 = (int)(unsigned)v0, s1 = (int)(unsigned)v1;
        int s2 = (int)(unsigned)v2, s3 = (int)(unsigned)v3;
        float w0 = __uint_as_float((unsigned)(v0 >> 32));
        float w1 = __uint_as_float((unsigned)(v1 >> 32));
        float w2 = __uint_as_float((unsigned)(v2 >> 32));
        float w3 = __uint_as_float((unsigned)(v3 >> 32));
        if (active) {
            const float4 a0 = *(const float4*)&d_m[(size_t)s0 * C + lane * 4];
            const float4 a1 = *(const float4*)&d_m[(size_t)s1 * C + lane * 4];
            const float4 a2 = *(const float4*)&d_m[(size_t)s2 * C + lane * 4];
            const float4 a3 = *(const float4*)&d_m[(size_t)s3 * C + lane * 4];
            acc.x = fmaf(w0, a0.x, acc.x); acc.y = fmaf(w0, a0.y, acc.y);
            acc.z = fmaf(w0, a0.z, acc.z); acc.w = fmaf(w0, a0.w, acc.w);
            acc.x = fmaf(w1, a1.x, acc.x); acc.y = fmaf(w1, a1.y, acc.y);
            acc.z = fmaf(w1, a1.z, acc.z); acc.w = fmaf(w1, a1.w, acc.w);
            acc.x = fmaf(w2, a2.x, acc.x); acc.y = fmaf(w2, a2.y, acc.y);
            acc.z = fmaf(w2, a2.z, acc.z); acc.w = fmaf(w2, a2.w, acc.w);
            acc.x = fmaf(w3, a3.x, acc.x); acc.y = fmaf(w3, a3.y, acc.y);
            acc.z = fmaf(w3, a3.z, acc.z); acc.w = fmaf(w3, a3.w, acc.w);
        }
    }
    for (; e < end; e++) {
        unsigned long long v0 = d_e[e];
        int s0 = (int)(unsigned)v0;
        float w0 = __uint_as_float((unsigned)(v0 >> 32));
        if (active) {
            const float4 a0 = *(const float4*)&d_m[(size_t)s0 * C + lane * 4];
            acc.x = fmaf(w0, a0.x, acc.x); acc.y = fmaf(w0, a0.y, acc.y);
            acc.z = fmaf(w0, a0.z, acc.z); acc.w = fmaf(w0, a0.w, acc.w);
        }
    }
    if (active) *(float4*)&d_agg[(size_t)warp * C + lane * 4] = acc;
}

// ---------------- BN stats + fused ticketed finalize ----------------
#define ROWS_PER_BLOCK 128
__global__ void k_stats(const float* __restrict__ gamma,
                        const float* __restrict__ beta) {
    int c  = threadIdx.x;
    int ty = threadIdx.y;
    int r0 = blockIdx.x * ROWS_PER_BLOCK;
    int rend = min(r0 + ROWS_PER_BLOCK, NN);
    float s = 0.0f, q = 0.0f;
    for (int r = r0 + ty; r < rend; r += 4) {
        float v = d_agg[(size_t)r * C + c];
        s += v;
        q = fmaf(v, v, q);
    }
    __shared__ float sh_s[4][C], sh_q[4][C];
    __shared__ int is_last;
    sh_s[ty][c] = s;
    sh_q[ty][c] = q;
    __syncthreads();
    if (ty == 0) {
        d_psum[blockIdx.x * C + c] = sh_s[0][c] + sh_s[1][c] + sh_s[2][c] + sh_s[3][c];
        d_psq [blockIdx.x * C + c] = sh_q[0][c] + sh_q[1][c] + sh_q[2][c] + sh_q[3][c];
    }
    __threadfence();
    if (ty == 0 && c == 0) is_last = (atomicAdd(&d_ticket, 1) == gridDim.x - 1);
    __syncthreads();
    if (is_last) {
        float S = 0.0f, Q = 0.0f;
        for (int b = ty; b < SGRID; b += 4) {
            S += d_psum[b * C + c];
            Q += d_psq [b * C + c];
        }
        sh_s[ty][c] = S;
        sh_q[ty][c] = Q;
        __syncthreads();
        if (ty == 0) {
            S = sh_s[0][c] + sh_s[1][c] + sh_s[2][c] + sh_s[3][c];
            Q = sh_q[0][c] + sh_q[1][c] + sh_q[2][c] + sh_q[3][c];
            float mean = S * (1.0f / (float)NN);
            float var  = Q * (1.0f / (float)NN) - mean * mean;
            float rstd = rsqrtf(var + BN_EPS);
            float sc = rstd * gamma[c];
            d_scale[c] = sc;
            d_shift[c] = beta[c] - mean * sc;
            if (c == 0) d_ticket = 0;
        }
    }
}

// ---------------- fused pool + output head ----------------
__global__ void k_poolout(const float* __restrict__ Wout,
                          const float* __restrict__ bout,
                          float* __restrict__ out) {
    __shared__ float pool[C];
    const int g = blockIdx.x;
    const int t = threadIdx.x;
    const int r0 = d_gstart[g], r1 = d_gstart[g + 1];
    if (t < C) {
        float s = 0.0f;
        for (int r = r0; r < r1; r++) s += d_agg[(size_t)r * C + t];
        pool[t] = fmaf(d_scale[t], s, (float)(r1 - r0) * d_shift[t]);
    }
    __syncthreads();
    float acc = bout[t];
#pragma unroll 4
    for (int k = 0; k < C; k++)
        acc = fmaf(pool[k], Wout[(size_t)k * OUTC + t], acc);
    out[(size_t)g * OUTC + t] = acc > 0.0f ? acc : 0.1f * acc;
}

// ---------------- launch ----------------
extern "C" void kernel_launch(void* const* d_in, const int* in_sizes, int n_in,
                              void* d_out, int out_size) {
    const float *x = 0, *W0 = 0, *Wrest = 0, *bb = 0, *gamma = 0, *beta = 0,
                *Wout = 0, *bout = 0;
    const void *ei = 0, *batch = 0;
    for (int i = 0; i < n_in; i++) {
        switch (in_sizes[i]) {
            case 1650000: x     = (const float*)d_in[i]; break;
            case 1600000: ei    = d_in[i];               break;
            case 50000:   batch = d_in[i];               break;
            case 3300:    W0    = (const float*)d_in[i]; break;
            case 30000:   Wrest = (const float*)d_in[i]; break;
            case 20000:   Wout  = (const float*)d_in[i]; break;
            case 200:     bout  = (const float*)d_in[i]; break;
            case 400:
                if (!bb) bb = (const float*)d_in[i];
                else if (!gamma) gamma = (const float*)d_in[i];
                else beta = (const float*)d_in[i];
                break;
            default: break;
        }
    }
    if (!x)     x     = (const float*)d_in[0];
    if (!ei)    ei    = d_in[1];
    if (!batch) batch = d_in[2];
    if (!W0)    W0    = (const float*)d_in[3];
    if (!Wrest) Wrest = (const float*)d_in[4];
    if (!bb)    bb    = (const float*)d_in[5];
    if (!gamma) gamma = (const float*)d_in[6];
    if (!beta)  beta  = (const float*)d_in[7];
    if (!Wout)  Wout  = (const float*)d_in[8];
    if (!bout)  bout  = (const float*)d_in[9];
    float* out = (float*)d_out;

    cudaFuncSetAttribute(k_gemm100_wmma,
                         cudaFuncAttributeMaxDynamicSharedMemorySize, SMW);

    const dim3 gemm_blk(25, 8);
    const int gemm_grid   = (NN + MT - 1) / MT;
    const int wmma_grid   = (NN + MTW - 1) / MTW;      // 391
    const int gather_grid = (NN * 32 + 255) / 256;
    const dim3 stats_blk(C, 4);

    k_init<<<(NN + 255) / 256, 256>>>((const long long*)ei);
    k_prep<<<(EE + 255) / 256, 256>>>(ei, batch);
    k_scanAB<<<SBLK, 256>>>();
    k_scanC<<<SBLK, 256>>>();
    k_fillb<<<FILL_BLKS + 2, 256>>>();

    // layer 0: aggregate x, SIMT GEMM K=33 (+bias) -> agg, stats+finalize
    k_gatherX<<<(NN * 32 + 255) / 256, 256>>>(x);
    k_gemm<<<gemm_grid, gemm_blk>>>(W0, bb, KIN, 1);
    k_stats<<<SGRID, stats_blk>>>(gamma, beta);

    // layers 1-3: WMMA tensor-core GEMM + gather + stats
    for (int L = 1; L < 4; L++) {
        const float* W = Wrest + (size_t)(L - 1) * C * C;
        k_gemm100_wmma<<<wmma_grid, 256, SMW>>>(W);
        k_gather<<<gather_grid, 256>>>(bb + L * C);
        k_stats<<<SGRID, stats_blk>>>(gamma + L * C, beta + L * C);
    }

    k_poolout<<<NG, OUTC>>>(Wout, bout, out);
}